// round 8
// baseline (speedup 1.0000x reference)
#include <cuda_runtime.h>
#include <cstdint>

#define B_   1024
#define T_   64
#define D_   512
#define H_   512
#define G4_  2048   // 4*H

// ---------------- device scratch (no allocation allowed) --------------------
__device__ float g_xp[(size_t)T_ * B_ * G4_];   // 512 MB: x@W + bias, [T][B][4H]
__device__ float g_xt[(size_t)T_ * D_ * B_];    // 128 MB: tf32-rounded X, [T][D][B]
__device__ float g_w32[(size_t)D_ * G4_];       // 4 MB: tf32-rounded kernel [D][4H]
__device__ float g_u32[(size_t)H_ * G4_];       // 4 MB: tf32-rounded recurrent kernel
__device__ float g_hT[2][(size_t)H_ * B_];      // 2x2 MB: rounded h, TRANSPOSED [H][B], ping-pong
__device__ unsigned g_bar[8];                   // per-by-group step barrier counters

// ---------------- helpers ---------------------------------------------------
__device__ __forceinline__ uint32_t f2tf32(float f) {
    uint32_t r;
    asm("cvt.rna.tf32.f32 %0, %1;" : "=r"(r) : "f"(f));
    return r;
}
__device__ __forceinline__ float rtf(float f) { return __uint_as_float(f2tf32(f)); }

__device__ __forceinline__ void mma8(float* c, const uint32_t* a, const uint32_t* b) {
    asm volatile(
        "mma.sync.aligned.m16n8k8.row.col.f32.tf32.tf32.f32 "
        "{%0,%1,%2,%3}, {%4,%5,%6,%7}, {%8,%9}, {%0,%1,%2,%3};\n"
        : "+f"(c[0]), "+f"(c[1]), "+f"(c[2]), "+f"(c[3])
        : "r"(a[0]), "r"(a[1]), "r"(a[2]), "r"(a[3]),
          "r"(b[0]), "r"(b[1]));
}

__device__ __forceinline__ float sigm(float x) { return 1.0f / (1.0f + __expf(-x)); }
__device__ __forceinline__ float tanh_(float x) { return 1.0f - 2.0f / (__expf(2.0f * x) + 1.0f); }

__device__ __forceinline__ void cp16(uint32_t s, const void* g) {
    asm volatile("cp.async.cg.shared.global [%0], [%1], 16;\n" :: "r"(s), "l"(g));
}
__device__ __forceinline__ void cpcommit() { asm volatile("cp.async.commit_group;\n"); }
template<int N> __device__ __forceinline__ void cpwait() {
    asm volatile("cp.async.wait_group %0;\n" :: "n"(N));
}

// ---------------- prep kernels ----------------------------------------------
__global__ void round_wu(const float* __restrict__ W, const float* __restrict__ U) {
    const int i = blockIdx.x * blockDim.x + threadIdx.x;   // D_*G4_ = 1M each
    g_w32[i] = rtf(W[i]);
    g_u32[i] = rtf(U[i]);
}

// X[b][t][k] -> g_xt[t][k][b], rounded to tf32
__global__ void prep_xt(const float* __restrict__ X) {
    __shared__ float tile[32][33];
    const int t = blockIdx.z, k0 = blockIdx.x * 32, b0 = blockIdx.y * 32;
    const int tx = threadIdx.x, ty = threadIdx.y;
#pragma unroll
    for (int i = 0; i < 4; i++)
        tile[ty + i * 8][tx] = X[((size_t)(b0 + ty + i * 8) * T_ + t) * D_ + k0 + tx];
    __syncthreads();
#pragma unroll
    for (int i = 0; i < 4; i++)
        g_xt[((size_t)t * D_ + k0 + ty + i * 8) * B_ + b0 + tx] = rtf(tile[tx][ty + i * 8]);
}

__global__ void zero_state() {
    const int i = blockIdx.x * blockDim.x + threadIdx.x;   // B_*H_
    g_hT[0][i] = 0.0f;
    g_hT[1][i] = 0.0f;
    if (i < 8) g_bar[i] = 0u;
}

// ---------------- stage 1: pipelined tf32 GEMM (unchanged) ------------------
// XP = Xperm @ W + bias, tiles 128x128, grid (16, 512)
__global__ void __launch_bounds__(256, 2)
gemm_x(const float* __restrict__ bias)
{
    constexpr int AROW = 136, BROW = 136;
    constexpr int STW  = 16 * AROW + 16 * BROW;

    extern __shared__ __align__(16) uint32_t sm[];
    const uint32_t sbase = (uint32_t)__cvta_generic_to_shared(sm);

    const int tid = threadIdx.x;
    const int bx = blockIdx.x, by = blockIdx.y;

    const int tt = by >> 3;
    const float* Abase = g_xt + (size_t)tt * D_ * B_ + (by & 7) * 128;

    uint32_t offA[2];
    const float* aG[2];
#pragma unroll
    for (int c = 0; c < 2; c++) {
        const int q = tid + c * 256;
        const int k = q >> 5, m4 = (q & 31) * 4;
        offA[c] = (uint32_t)(k * AROW + m4);
        aG[c]   = Abase + (size_t)k * B_ + m4;
    }
    uint32_t offB[2];
    const float* bG[2];
#pragma unroll
    for (int c = 0; c < 2; c++) {
        const int q = tid + c * 256;
        const int k = q >> 5, m4 = (q & 31) * 4;
        offB[c] = (uint32_t)(16 * AROW + k * BROW + m4);
        bG[c] = g_w32 + (size_t)k * G4_ + bx * 128 + m4;
    }

    const int warp = tid >> 5, lane = tid & 31;
    const int wm = warp >> 2, wn = warp & 3;
    const int gq = lane >> 2, tq = lane & 3;

    float acc[4][4][4] = {};

    auto ISSUE = [&](int kt, int s) {
#pragma unroll
        for (int c = 0; c < 2; c++)
            cp16(sbase + (uint32_t)(s * STW + offA[c]) * 4u, aG[c] + (size_t)kt * 16 * B_);
#pragma unroll
        for (int c = 0; c < 2; c++)
            cp16(sbase + (uint32_t)(s * STW + offB[c]) * 4u, bG[c] + (size_t)kt * 16 * G4_);
    };

    ISSUE(0, 0); cpcommit();
    ISSUE(1, 1); cpcommit();

    for (int kt = 0; kt < D_ / 16; kt++) {
        cpwait<1>();
        __syncthreads();
        if (kt + 2 < D_ / 16) ISSUE(kt + 2, (kt + 2) % 3);
        cpcommit();

        const uint32_t* As  = sm + (kt % 3) * STW;
        const uint32_t* Bsm = As + 16 * AROW;
#pragma unroll
        for (int k8 = 0; k8 < 16; k8 += 8) {
            uint32_t afr[4][4], bfr[4][2];
#pragma unroll
            for (int mf = 0; mf < 4; mf++) {
                const int r0 = wm * 64 + mf * 16 + gq;
                afr[mf][0] = As[(k8 + tq) * AROW + r0];
                afr[mf][1] = As[(k8 + tq) * AROW + r0 + 8];
                afr[mf][2] = As[(k8 + tq + 4) * AROW + r0];
                afr[mf][3] = As[(k8 + tq + 4) * AROW + r0 + 8];
            }
#pragma unroll
            for (int nf = 0; nf < 4; nf++) {
                const int c0 = wn * 32 + nf * 8 + gq;
                bfr[nf][0] = Bsm[(k8 + tq) * BROW + c0];
                bfr[nf][1] = Bsm[(k8 + tq + 4) * BROW + c0];
            }
#pragma unroll
            for (int mf = 0; mf < 4; mf++)
#pragma unroll
                for (int nf = 0; nf < 4; nf++)
                    mma8(acc[mf][nf], afr[mf], bfr[nf]);
        }
    }
    __syncthreads();

    const int n0 = bx * 128;
#pragma unroll
    for (int mf = 0; mf < 4; mf++)
#pragma unroll
        for (int nf = 0; nf < 4; nf++) {
            const int row = by * 128 + wm * 64 + mf * 16 + gq;   // = t*B_ + b
            const int col = n0 + wn * 32 + nf * 8 + tq * 2;
            const float b0v = bias[col], b1v = bias[col + 1];
            float2 v0 = make_float2(acc[mf][nf][0] + b0v, acc[mf][nf][1] + b1v);
            float2 v1 = make_float2(acc[mf][nf][2] + b0v, acc[mf][nf][3] + b1v);
            *(float2*)&g_xp[(size_t)row * G4_ + col] = v0;
            *(float2*)&g_xp[(size_t)(row + 8) * G4_ + col] = v1;
        }
}

// ---------------- stage 2: persistent recurrent kernel ----------------------
// grid (16, 8) = 128 CTAs, 512 threads each (1 CTA/SM, balanced).
// bx = 32-hid slice; by = 128-batch slice. 16 warps, warp tile 32x32.
// All 64 steps inside; per-by-group (16 CTA) spin barrier between steps.
__global__ void __launch_bounds__(512, 1)
lstm_rec(float* __restrict__ out)
{
    constexpr int AROW = 136, BROW = 136;
    constexpr int STW  = 16 * AROW + 16 * BROW;   // 4352 words
    constexpr int XPW  = 3 * STW;                 // xp smem offset (words)
    constexpr int XROW = 132;                     // xp row stride (padded)

    extern __shared__ __align__(16) uint32_t sm[];
    const uint32_t sbase = (uint32_t)__cvta_generic_to_shared(sm);
    const float* xp_sm = (const float*)sm + XPW;

    const int tid = threadIdx.x;
    const int bx = blockIdx.x, by = blockIdx.y;

    // ---- A (h) loader: 1 chunk per thread covers 16k x 128 rows
    const int ka  = tid >> 5;               // 0..15
    const int am4 = (tid & 31) * 4;         // 0..124
    const uint32_t offA = (uint32_t)(ka * AROW + am4);
    const size_t   aoff = (size_t)ka * B_ + by * 128 + am4;

    // ---- B (U) loader: 1 chunk per thread (gate-major cols)
    const uint32_t offB = (uint32_t)(16 * AROW + ka * BROW + am4);
    const int bgate = am4 >> 5, bhid = am4 & 31;
    const float* bG = g_u32 + (size_t)ka * G4_ + bgate * H_ + bx * 32 + bhid;

    // ---- xp loader: 8 chunks x (16 rows x 128 cols), during kt<8
    const int xr = tid >> 5;                // row 0..15
    const int xc = (tid & 31) * 4;          // col 0..124
    const size_t xsrc0 = ((size_t)(by * 128 + xr)) * G4_
                       + (xc >> 5) * H_ + bx * 32 + (xc & 31);

    const int warp = tid >> 5, lane = tid & 31;
    const int wm = warp >> 2, wn = warp & 3;  // wm 0..3: 32 rows each
    const int gq = lane >> 2, tq = lane & 3;
    const int hidl = wn * 8 + tq * 2;

    float cst[2][2][2] = {};                // cell state, registers only

    for (int t = 0; t < T_; t++) {
        const float* hbase = g_hT[t & 1];
        float*       hW    = g_hT[(t + 1) & 1];
        const size_t xstep = (size_t)t * B_ * G4_;

        float acc[2][4][4] = {};

        auto ISSUE = [&](int kt) {
            const uint32_t sb = sbase + (uint32_t)((kt % 3) * STW) * 4u;
            cp16(sb + offA * 4u, hbase + aoff + (size_t)kt * 16 * B_);
            cp16(sb + offB * 4u, bG + (size_t)kt * 16 * G4_);
            if (kt < 8)
                cp16(sbase + (uint32_t)(XPW + (xr + 16 * kt) * XROW + xc) * 4u,
                     g_xp + xstep + xsrc0 + (size_t)(16 * kt) * G4_);
        };

        ISSUE(0); cpcommit();
        ISSUE(1); cpcommit();

        for (int kt = 0; kt < H_ / 16; kt++) {
            cpwait<1>();
            __syncthreads();
            if (kt + 2 < H_ / 16) ISSUE(kt + 2);
            cpcommit();

            const uint32_t* As  = sm + (kt % 3) * STW;
            const uint32_t* Bsm = As + 16 * AROW;
#pragma unroll
            for (int k8 = 0; k8 < 16; k8 += 8) {
                uint32_t afr[2][4], bfr[4][2];
#pragma unroll
                for (int mf = 0; mf < 2; mf++) {
                    const int r0 = wm * 32 + mf * 16 + gq;
                    afr[mf][0] = As[(k8 + tq) * AROW + r0];
                    afr[mf][1] = As[(k8 + tq) * AROW + r0 + 8];
                    afr[mf][2] = As[(k8 + tq + 4) * AROW + r0];
                    afr[mf][3] = As[(k8 + tq + 4) * AROW + r0 + 8];
                }
#pragma unroll
                for (int nf = 0; nf < 4; nf++) {
                    const int c0 = nf * 32 + wn * 8 + gq;
                    bfr[nf][0] = Bsm[(k8 + tq) * BROW + c0];
                    bfr[nf][1] = Bsm[(k8 + tq + 4) * BROW + c0];
                }
#pragma unroll
                for (int mf = 0; mf < 2; mf++)
#pragma unroll
                    for (int nf = 0; nf < 4; nf++)
                        mma8(acc[mf][nf], afr[mf], bfr[nf]);
            }
        }

        // ---- fused LSTM cell epilogue (xp from smem, c in registers)
#pragma unroll
        for (int mf = 0; mf < 2; mf++) {
#pragma unroll
            for (int rh = 0; rh < 2; rh++) {
                const int rl = wm * 32 + mf * 16 + rh * 8 + gq;   // local batch row
                float z[4][2];
#pragma unroll
                for (int g = 0; g < 4; g++) {
                    z[g][0] = acc[mf][g][rh * 2 + 0] + xp_sm[rl * XROW + g * 32 + hidl];
                    z[g][1] = acc[mf][g][rh * 2 + 1] + xp_sm[rl * XROW + g * 32 + hidl + 1];
                }
                float2 hh;
                {
                    const float ii = sigm(z[0][0]), ff = sigm(z[1][0]);
                    const float gg = tanh_(z[2][0]), oo = sigm(z[3][0]);
                    cst[mf][rh][0] = ff * cst[mf][rh][0] + ii * gg;
                    hh.x = oo * tanh_(cst[mf][rh][0]);
                }
                {
                    const float ii = sigm(z[0][1]), ff = sigm(z[1][1]);
                    const float gg = tanh_(z[2][1]), oo = sigm(z[3][1]);
                    cst[mf][rh][1] = ff * cst[mf][rh][1] + ii * gg;
                    hh.y = oo * tanh_(cst[mf][rh][1]);
                }
                const int r = by * 128 + rl;
                *(float2*)&out[((size_t)r * T_ + t) * H_ + bx * 32 + hidl] = hh;
                hW[(size_t)(bx * 32 + hidl) * B_ + r]     = rtf(hh.x);
                hW[(size_t)(bx * 32 + hidl + 1) * B_ + r] = rtf(hh.y);
            }
        }

        // ---- per-by-group step barrier (16 CTAs)
        __syncthreads();
        if (tid == 0) {
            __threadfence();
            atomicAdd(&g_bar[by], 1u);
            const unsigned tgt = 16u * (unsigned)(t + 1);
            unsigned v;
            do {
                asm volatile("ld.acquire.gpu.u32 %0, [%1];"
                             : "=r"(v) : "l"(&g_bar[by]) : "memory");
                if (v < tgt) __nanosleep(20);
            } while (v < tgt);
        }
        __syncthreads();
    }
}

// ---------------- launch -----------------------------------------------------
extern "C" void kernel_launch(void* const* d_in, const int* in_sizes, int n_in,
                              void* d_out, int out_size)
{
    const float* X    = (const float*)d_in[0];   // [B, T, D]
    const float* W    = (const float*)d_in[1];   // [D, 4H]
    const float* U    = (const float*)d_in[2];   // [H, 4H]
    const float* bias = (const float*)d_in[3];   // [4H]
    float* out = (float*)d_out;                  // [B, T, H]

    constexpr int SM0 = 3 * (16 * 136 + 16 * 136) * 4;              // 52224 B
    constexpr int SM1 = (3 * (16 * 136 + 16 * 136) + 128 * 132) * 4; // 119808 B
    cudaFuncSetAttribute(gemm_x,   cudaFuncAttributeMaxDynamicSharedMemorySize, SM0);
    cudaFuncSetAttribute(lstm_rec, cudaFuncAttributeMaxDynamicSharedMemorySize, SM1);

    round_wu<<<(D_ * G4_) / 256, 256>>>(W, U);
    prep_xt<<<dim3(D_ / 32, B_ / 32, T_), dim3(32, 8)>>>(X);
    zero_state<<<(B_ * H_) / 256, 256>>>();

    // Stage 1: input projection (128x128 tiles)
    gemm_x<<<dim3(G4_ / 128, (T_ * B_) / 128), 256, SM0>>>(bias);

    // Stage 2: single persistent kernel, 128 balanced CTAs, all 64 steps
    lstm_rec<<<dim3(16, 8), 512, SM1>>>(out);
}

// round 9
// speedup vs baseline: 1.3184x; 1.3184x over previous
#include <cuda_runtime.h>
#include <cuda_fp16.h>
#include <cstdint>

#define B_   1024
#define T_   64
#define D_   512
#define H_   512
#define G4_  2048   // 4*H

// ---------------- device scratch (no allocation allowed) --------------------
__device__ float   g_xp[(size_t)T_ * B_ * G4_];        // 512 MB: x@W + bias, [T][B][4H]
__device__ __half2 g_xh2[(size_t)T_ * (D_/2) * B_];    // 64 MB: X, [t][k2][b] k-pair interleaved
__device__ __half2 g_wh2[(size_t)(D_/2) * G4_];        // 2 MB: W, [k2][n]
__device__ __half2 g_uh2[(size_t)(H_/2) * G4_];        // 2 MB: U, [k2][n]
__device__ __half2 g_h2[2][(size_t)(H_/2) * B_];       // 2x1 MB: h, [h2][b], ping-pong
__device__ unsigned g_bar[8];                          // per-by-group step barriers

// ---------------- helpers ---------------------------------------------------
__device__ __forceinline__ void mma16(float* c, const uint32_t* a, const uint32_t* b) {
    asm volatile(
        "mma.sync.aligned.m16n8k16.row.col.f32.f16.f16.f32 "
        "{%0,%1,%2,%3}, {%4,%5,%6,%7}, {%8,%9}, {%0,%1,%2,%3};\n"
        : "+f"(c[0]), "+f"(c[1]), "+f"(c[2]), "+f"(c[3])
        : "r"(a[0]), "r"(a[1]), "r"(a[2]), "r"(a[3]),
          "r"(b[0]), "r"(b[1]));
}

__device__ __forceinline__ float sigm(float x) { return 1.0f / (1.0f + __expf(-x)); }
__device__ __forceinline__ float tanh_(float x) { return 1.0f - 2.0f / (__expf(2.0f * x) + 1.0f); }

__device__ __forceinline__ void cp16(uint32_t s, const void* g) {
    asm volatile("cp.async.cg.shared.global [%0], [%1], 16;\n" :: "r"(s), "l"(g));
}
__device__ __forceinline__ void cpcommit() { asm volatile("cp.async.commit_group;\n"); }
template<int N> __device__ __forceinline__ void cpwait() {
    asm volatile("cp.async.wait_group %0;\n" :: "n"(N));
}

// ---------------- prep kernels ----------------------------------------------
// W/U [D][4H] fp32 -> [k2][4H] half2 (k-pair interleaved)
__global__ void conv_wu(const float* __restrict__ W, const float* __restrict__ U) {
    const int i = blockIdx.x * blockDim.x + threadIdx.x;  // (D/2)*G4 = 512K
    const int n = i & (G4_ - 1), k2 = i >> 11;
    g_wh2[i] = __floats2half2_rn(W[(size_t)(2 * k2) * G4_ + n], W[(size_t)(2 * k2 + 1) * G4_ + n]);
    g_uh2[i] = __floats2half2_rn(U[(size_t)(2 * k2) * G4_ + n], U[(size_t)(2 * k2 + 1) * G4_ + n]);
}

// X[b][t][k] fp32 -> g_xh2[t][k2][b] half2
__global__ void prep_xh(const float* __restrict__ X) {
    __shared__ float tile[32][33];   // [b_local][k_local]
    const int t = blockIdx.z, k0 = blockIdx.x * 32, b0 = blockIdx.y * 32;
    const int tx = threadIdx.x, ty = threadIdx.y;
#pragma unroll
    for (int i = 0; i < 4; i++)
        tile[ty + i * 8][tx] = X[((size_t)(b0 + ty + i * 8) * T_ + t) * D_ + k0 + tx];
    __syncthreads();
#pragma unroll
    for (int i = 0; i < 2; i++) {
        const int k2 = ty + i * 8;   // 0..15
        g_xh2[((size_t)t * (D_ / 2) + (k0 >> 1) + k2) * B_ + b0 + tx] =
            __floats2half2_rn(tile[tx][2 * k2], tile[tx][2 * k2 + 1]);
    }
}

__global__ void zero_state() {
    const int i = blockIdx.x * blockDim.x + threadIdx.x;   // (H/2)*B = 262144
    const __half2 z = __floats2half2_rn(0.0f, 0.0f);
    g_h2[0][i] = z;
    g_h2[1][i] = z;
    if (i < 8) g_bar[i] = 0u;
}

// ---------------- stage 1: fp16 pipelined GEMM ------------------------------
// XP = Xperm @ W + bias, tiles 128x128, KC=32, grid (16, 512), 256 thr, 2 CTA/SM
__global__ void __launch_bounds__(256, 2)
gemm_x(const float* __restrict__ bias)
{
    constexpr int AROW = 132, BROW = 132;          // words; mod 32 == 4 -> conflict-free
    constexpr int STW  = 16 * AROW + 16 * BROW;    // 4224 words per stage

    extern __shared__ __align__(16) uint32_t sm[];
    const uint32_t sbase = (uint32_t)__cvta_generic_to_shared(sm);

    const int tid = threadIdx.x;
    const int bx = blockIdx.x, by = blockIdx.y;

    const int tt = by >> 3, m0 = (by & 7) * 128;
    const __half2* Ab = g_xh2 + (size_t)tt * (D_ / 2) * B_ + m0;

    // loaders: 2x16B each for A and B per chunk (chunk = 16 k2-rows x 128 cols)
    uint32_t offA[2], offB[2];
    const __half2* aG[2];
    const __half2* bG[2];
#pragma unroll
    for (int c = 0; c < 2; c++) {
        const int q = tid + c * 256;
        const int k2 = q >> 5, m4 = (q & 31) * 4;
        offA[c] = (uint32_t)(k2 * AROW + m4);
        aG[c]   = Ab + (size_t)k2 * B_ + m4;
        offB[c] = (uint32_t)(16 * AROW + k2 * BROW + m4);
        bG[c]   = g_wh2 + (size_t)k2 * G4_ + bx * 128 + m4;
    }

    const int warp = tid >> 5, lane = tid & 31;
    const int wm = warp >> 2, wn = warp & 3;
    const int gq = lane >> 2, tq = lane & 3;

    float acc[4][4][4] = {};

    auto ISSUE = [&](int kt, int s) {
#pragma unroll
        for (int c = 0; c < 2; c++) {
            cp16(sbase + (uint32_t)(s * STW + offA[c]) * 4u, aG[c] + (size_t)kt * 16 * B_);
            cp16(sbase + (uint32_t)(s * STW + offB[c]) * 4u, bG[c] + (size_t)kt * 16 * G4_);
        }
    };

    ISSUE(0, 0); cpcommit();
    ISSUE(1, 1); cpcommit();

    for (int kt = 0; kt < 16; kt++) {              // 16 chunks of k=32
        cpwait<1>();
        __syncthreads();
        if (kt + 2 < 16) ISSUE(kt + 2, (kt + 2) % 3);
        cpcommit();

        const uint32_t* As  = sm + (kt % 3) * STW;
        const uint32_t* Bsm = As + 16 * AROW;
#pragma unroll
        for (int j = 0; j < 2; j++) {              // two k16 mma groups
            uint32_t afr[4][4], bfr[4][2];
#pragma unroll
            for (int mf = 0; mf < 4; mf++) {
                const int r0 = wm * 64 + mf * 16 + gq;
                afr[mf][0] = As[(8 * j + tq) * AROW + r0];
                afr[mf][1] = As[(8 * j + tq) * AROW + r0 + 8];
                afr[mf][2] = As[(8 * j + tq + 4) * AROW + r0];
                afr[mf][3] = As[(8 * j + tq + 4) * AROW + r0 + 8];
            }
#pragma unroll
            for (int nf = 0; nf < 4; nf++) {
                const int c0 = wn * 32 + nf * 8 + gq;
                bfr[nf][0] = Bsm[(8 * j + tq) * BROW + c0];
                bfr[nf][1] = Bsm[(8 * j + tq + 4) * BROW + c0];
            }
#pragma unroll
            for (int mf = 0; mf < 4; mf++)
#pragma unroll
                for (int nf = 0; nf < 4; nf++)
                    mma16(acc[mf][nf], afr[mf], bfr[nf]);
        }
    }
    __syncthreads();

    const int n0 = bx * 128;
#pragma unroll
    for (int mf = 0; mf < 4; mf++)
#pragma unroll
        for (int nf = 0; nf < 4; nf++) {
            const int row = by * 128 + wm * 64 + mf * 16 + gq;   // = t*B_ + b
            const int col = n0 + wn * 32 + nf * 8 + tq * 2;
            const float b0v = bias[col], b1v = bias[col + 1];
            float2 v0 = make_float2(acc[mf][nf][0] + b0v, acc[mf][nf][1] + b1v);
            float2 v1 = make_float2(acc[mf][nf][2] + b0v, acc[mf][nf][3] + b1v);
            *(float2*)&g_xp[(size_t)row * G4_ + col] = v0;
            *(float2*)&g_xp[(size_t)(row + 8) * G4_ + col] = v1;
        }
}

// ---------------- stage 2: persistent fp16 recurrent kernel -----------------
// grid (16, 8) = 128 CTAs, 512 thr, 1 CTA/SM. bx = 32-hid slice; by = 128-batch.
// KC=32 (16 chunks); xp prefetched to smem; c in registers; per-by barrier.
__global__ void __launch_bounds__(512, 1)
lstm_rec(float* __restrict__ out)
{
    constexpr int AROW = 132, BROW = 132;
    constexpr int STW  = 16 * AROW + 16 * BROW;   // 4224 words
    constexpr int XPW  = 3 * STW;                 // 12672 words
    constexpr int XROW = 132;

    extern __shared__ __align__(16) uint32_t sm[];
    const uint32_t sbase = (uint32_t)__cvta_generic_to_shared(sm);
    const float* xp_sm = (const float*)sm + XPW;

    const int tid = threadIdx.x;
    const int bx = blockIdx.x, by = blockIdx.y;

    // A (h) loader: 512 thr x 16B = 8KB chunk (16 k2 x 128 b)
    const int ak2 = tid >> 5, am4 = (tid & 31) * 4;
    const uint32_t offA = (uint32_t)(ak2 * AROW + am4);
    const size_t   aoff = (size_t)ak2 * B_ + by * 128 + am4;

    // B (U) loader: gate-major local cols
    const uint32_t offB = (uint32_t)(16 * AROW + ak2 * BROW + am4);
    const int bgate = am4 >> 5, bhid = am4 & 31;
    const __half2* bG = g_uh2 + (size_t)ak2 * G4_ + bgate * H_ + bx * 32 + bhid;

    // xp loader: 16 rows x 128 cols fp32 per chunk, first 8 chunks
    const int xr = tid >> 5;                // 0..15
    const int xc = (tid & 31) * 4;
    const size_t xsrc0 = ((size_t)(by * 128 + xr)) * G4_
                       + (xc >> 5) * H_ + bx * 32 + (xc & 31);

    const int warp = tid >> 5, lane = tid & 31;
    const int wm = warp >> 2, wn = warp & 3;
    const int gq = lane >> 2, tq = lane & 3;
    const int hidl = wn * 8 + tq * 2;

    float cst[2][2][2] = {};                // cell state, registers only

    for (int t = 0; t < T_; t++) {
        const __half2* hbase = g_h2[t & 1];
        __half2*       hW    = g_h2[(t + 1) & 1];
        const size_t xstep = (size_t)t * B_ * G4_;

        float acc[2][4][4] = {};

        auto ISSUE = [&](int kt) {
            const uint32_t sb = sbase + (uint32_t)((kt % 3) * STW) * 4u;
            cp16(sb + offA * 4u, hbase + aoff + (size_t)kt * 16 * B_);
            cp16(sb + offB * 4u, bG + (size_t)kt * 16 * G4_);
            if (kt < 8)
                cp16(sbase + (uint32_t)(XPW + (xr + 16 * kt) * XROW + xc) * 4u,
                     g_xp + xstep + xsrc0 + (size_t)(16 * kt) * G4_);
        };

        ISSUE(0); cpcommit();
        ISSUE(1); cpcommit();

        for (int kt = 0; kt < 16; kt++) {
            cpwait<1>();
            __syncthreads();
            if (kt + 2 < 16) ISSUE(kt + 2);
            cpcommit();

            const uint32_t* As  = sm + (kt % 3) * STW;
            const uint32_t* Bsm = As + 16 * AROW;
#pragma unroll
            for (int j = 0; j < 2; j++) {
                uint32_t afr[2][4], bfr[4][2];
#pragma unroll
                for (int mf = 0; mf < 2; mf++) {
                    const int r0 = wm * 32 + mf * 16 + gq;
                    afr[mf][0] = As[(8 * j + tq) * AROW + r0];
                    afr[mf][1] = As[(8 * j + tq) * AROW + r0 + 8];
                    afr[mf][2] = As[(8 * j + tq + 4) * AROW + r0];
                    afr[mf][3] = As[(8 * j + tq + 4) * AROW + r0 + 8];
                }
#pragma unroll
                for (int nf = 0; nf < 4; nf++) {
                    const int c0 = nf * 32 + wn * 8 + gq;
                    bfr[nf][0] = Bsm[(8 * j + tq) * BROW + c0];
                    bfr[nf][1] = Bsm[(8 * j + tq + 4) * BROW + c0];
                }
#pragma unroll
                for (int mf = 0; mf < 2; mf++)
#pragma unroll
                    for (int nf = 0; nf < 4; nf++)
                        mma16(acc[mf][nf], afr[mf], bfr[nf]);
            }
        }

        // ---- fused LSTM cell epilogue
#pragma unroll
        for (int mf = 0; mf < 2; mf++) {
#pragma unroll
            for (int rh = 0; rh < 2; rh++) {
                const int rl = wm * 32 + mf * 16 + rh * 8 + gq;   // local batch row
                float z[4][2];
#pragma unroll
                for (int g = 0; g < 4; g++) {
                    z[g][0] = acc[mf][g][rh * 2 + 0] + xp_sm[rl * XROW + g * 32 + hidl];
                    z[g][1] = acc[mf][g][rh * 2 + 1] + xp_sm[rl * XROW + g * 32 + hidl + 1];
                }
                float2 hh;
                {
                    const float ii = sigm(z[0][0]), ff = sigm(z[1][0]);
                    const float gg = tanh_(z[2][0]), oo = sigm(z[3][0]);
                    cst[mf][rh][0] = ff * cst[mf][rh][0] + ii * gg;
                    hh.x = oo * tanh_(cst[mf][rh][0]);
                }
                {
                    const float ii = sigm(z[0][1]), ff = sigm(z[1][1]);
                    const float gg = tanh_(z[2][1]), oo = sigm(z[3][1]);
                    cst[mf][rh][1] = ff * cst[mf][rh][1] + ii * gg;
                    hh.y = oo * tanh_(cst[mf][rh][1]);
                }
                const int r = by * 128 + rl;
                *(float2*)&out[((size_t)r * T_ + t) * H_ + bx * 32 + hidl] = hh;
                // k-pair-interleaved fp16 h for the next step's A operand
                hW[(size_t)(bx * 16 + (hidl >> 1)) * B_ + r] = __floats2half2_rn(hh.x, hh.y);
            }
        }

        // ---- per-by-group step barrier (16 CTAs)
        __syncthreads();
        if (tid == 0) {
            __threadfence();
            atomicAdd(&g_bar[by], 1u);
            const unsigned tgt = 16u * (unsigned)(t + 1);
            unsigned v;
            do {
                asm volatile("ld.acquire.gpu.u32 %0, [%1];"
                             : "=r"(v) : "l"(&g_bar[by]) : "memory");
                if (v < tgt) __nanosleep(20);
            } while (v < tgt);
        }
        __syncthreads();
    }
}

// ---------------- launch -----------------------------------------------------
extern "C" void kernel_launch(void* const* d_in, const int* in_sizes, int n_in,
                              void* d_out, int out_size)
{
    const float* X    = (const float*)d_in[0];   // [B, T, D]
    const float* W    = (const float*)d_in[1];   // [D, 4H]
    const float* U    = (const float*)d_in[2];   // [H, 4H]
    const float* bias = (const float*)d_in[3];   // [4H]
    float* out = (float*)d_out;                  // [B, T, H]

    constexpr int SM0 = 3 * 4224 * 4;                     // 50688 B
    constexpr int SM1 = (3 * 4224 + 128 * 132) * 4;       // 118272 B
    cudaFuncSetAttribute(gemm_x,   cudaFuncAttributeMaxDynamicSharedMemorySize, SM0);
    cudaFuncSetAttribute(lstm_rec, cudaFuncAttributeMaxDynamicSharedMemorySize, SM1);

    conv_wu<<<((D_ / 2) * G4_) / 256, 256>>>(W, U);
    prep_xh<<<dim3(D_ / 32, B_ / 32, T_), dim3(32, 8)>>>(X);
    zero_state<<<((H_ / 2) * B_) / 256, 256>>>();

    // Stage 1: input projection (128x128 tiles, fp16 operands)
    gemm_x<<<dim3(G4_ / 128, (T_ * B_) / 128), 256, SM0>>>(bias);

    // Stage 2: single persistent kernel, 128 balanced CTAs, all 64 steps
    lstm_rec<<<dim3(16, 8), 512, SM1>>>(out);
}

// round 10
// speedup vs baseline: 1.6248x; 1.2324x over previous
#include <cuda_runtime.h>
#include <cuda_fp16.h>
#include <cstdint>

#define B_   1024
#define T_   64
#define D_   512
#define H_   512
#define G4_  2048   // 4*H

// ---------------- device scratch (no allocation allowed) --------------------
__device__ __half2 g_xph[(size_t)T_ * B_ * (G4_/2)];   // 256 MB: x@W + bias, [t][b][n2] half2
__device__ __half2 g_xh2[(size_t)T_ * (D_/2) * B_];    // 64 MB: X, [t][k2][b]
__device__ __half2 g_wh2[(size_t)(D_/2) * G4_];        // 2 MB: W, [k2][n]
__device__ __half2 g_uh2[(size_t)(H_/2) * G4_];        // 2 MB: U, [k2][n]
__device__ __half2 g_h2[2][(size_t)(H_/2) * B_];       // 2x1 MB: h, [k2][b], ping-pong
__device__ unsigned g_bar[8];                          // per-by-group step barriers

// ---------------- helpers ---------------------------------------------------
__device__ __forceinline__ void mma16(float* c, const uint32_t* a, const uint32_t* b) {
    asm volatile(
        "mma.sync.aligned.m16n8k16.row.col.f32.f16.f16.f32 "
        "{%0,%1,%2,%3}, {%4,%5,%6,%7}, {%8,%9}, {%0,%1,%2,%3};\n"
        : "+f"(c[0]), "+f"(c[1]), "+f"(c[2]), "+f"(c[3])
        : "r"(a[0]), "r"(a[1]), "r"(a[2]), "r"(a[3]),
          "r"(b[0]), "r"(b[1]));
}

__device__ __forceinline__ float sigm(float x) { return 1.0f / (1.0f + __expf(-x)); }
__device__ __forceinline__ float tanh_(float x) { return 1.0f - 2.0f / (__expf(2.0f * x) + 1.0f); }

__device__ __forceinline__ void cp16(uint32_t s, const void* g) {
    asm volatile("cp.async.cg.shared.global [%0], [%1], 16;\n" :: "r"(s), "l"(g));
}
__device__ __forceinline__ void cpcommit() { asm volatile("cp.async.commit_group;\n"); }
template<int N> __device__ __forceinline__ void cpwait() {
    asm volatile("cp.async.wait_group %0;\n" :: "n"(N));
}

// ---------------- prep kernels ----------------------------------------------
__global__ void conv_wu(const float* __restrict__ W, const float* __restrict__ U) {
    const int i = blockIdx.x * blockDim.x + threadIdx.x;  // (D/2)*G4 = 512K
    const int n = i & (G4_ - 1), k2 = i >> 11;
    g_wh2[i] = __floats2half2_rn(W[(size_t)(2 * k2) * G4_ + n], W[(size_t)(2 * k2 + 1) * G4_ + n]);
    g_uh2[i] = __floats2half2_rn(U[(size_t)(2 * k2) * G4_ + n], U[(size_t)(2 * k2 + 1) * G4_ + n]);
}

// X[b][t][k] fp32 -> g_xh2[t][k2][b] half2
__global__ void prep_xh(const float* __restrict__ X) {
    __shared__ float tile[32][33];   // [b_local][k_local]
    const int t = blockIdx.z, k0 = blockIdx.x * 32, b0 = blockIdx.y * 32;
    const int tx = threadIdx.x, ty = threadIdx.y;
#pragma unroll
    for (int i = 0; i < 4; i++)
        tile[ty + i * 8][tx] = X[((size_t)(b0 + ty + i * 8) * T_ + t) * D_ + k0 + tx];
    __syncthreads();
#pragma unroll
    for (int i = 0; i < 2; i++) {
        const int k2 = ty + i * 8;   // 0..15
        g_xh2[((size_t)t * (D_ / 2) + (k0 >> 1) + k2) * B_ + b0 + tx] =
            __floats2half2_rn(tile[tx][2 * k2], tile[tx][2 * k2 + 1]);
    }
}

__global__ void zero_state() {
    const int i = blockIdx.x * blockDim.x + threadIdx.x;   // (H/2)*B = 262144
    const __half2 z = __floats2half2_rn(0.0f, 0.0f);
    g_h2[0][i] = z;
    g_h2[1][i] = z;
    if (i < 8) g_bar[i] = 0u;
}

// ---------------- stage 1: fp16 pipelined GEMM ------------------------------
// XP = Xperm @ W + bias (-> half2), tiles 128x128, KC=32, grid (16,512), 2 CTA/SM
__global__ void __launch_bounds__(256, 2)
gemm_x(const float* __restrict__ bias)
{
    constexpr int AROW = 136, BROW = 136;          // mod 32 == 8 -> conflict-free
    constexpr int STW  = 16 * AROW + 16 * BROW;    // 4352 words per stage

    extern __shared__ __align__(16) uint32_t sm[];
    const uint32_t sbase = (uint32_t)__cvta_generic_to_shared(sm);

    const int tid = threadIdx.x;
    const int bx = blockIdx.x, by = blockIdx.y;

    const int tt = by >> 3, m0 = (by & 7) * 128;
    const __half2* Ab = g_xh2 + (size_t)tt * (D_ / 2) * B_ + m0;

    uint32_t offA[2], offB[2];
    const __half2* aG[2];
    const __half2* bG[2];
#pragma unroll
    for (int c = 0; c < 2; c++) {
        const int q = tid + c * 256;
        const int k2 = q >> 5, m4 = (q & 31) * 4;
        offA[c] = (uint32_t)(k2 * AROW + m4);
        aG[c]   = Ab + (size_t)k2 * B_ + m4;
        offB[c] = (uint32_t)(16 * AROW + k2 * BROW + m4);
        bG[c]   = g_wh2 + (size_t)k2 * G4_ + bx * 128 + m4;
    }

    const int warp = tid >> 5, lane = tid & 31;
    const int wm = warp >> 2, wn = warp & 3;
    const int gq = lane >> 2, tq = lane & 3;

    float acc[4][4][4] = {};

    auto ISSUE = [&](int kt, int s) {
#pragma unroll
        for (int c = 0; c < 2; c++) {
            cp16(sbase + (uint32_t)(s * STW + offA[c]) * 4u, aG[c] + (size_t)kt * 16 * B_);
            cp16(sbase + (uint32_t)(s * STW + offB[c]) * 4u, bG[c] + (size_t)kt * 16 * G4_);
        }
    };

    ISSUE(0, 0); cpcommit();
    ISSUE(1, 1); cpcommit();

    for (int kt = 0; kt < 16; kt++) {              // 16 chunks of k=32
        cpwait<1>();
        __syncthreads();
        if (kt + 2 < 16) ISSUE(kt + 2, (kt + 2) % 3);
        cpcommit();

        const uint32_t* As  = sm + (kt % 3) * STW;
        const uint32_t* Bsm = As + 16 * AROW;
#pragma unroll
        for (int j = 0; j < 2; j++) {
            uint32_t afr[4][4], bfr[4][2];
#pragma unroll
            for (int mf = 0; mf < 4; mf++) {
                const int r0 = wm * 64 + mf * 16 + gq;
                afr[mf][0] = As[(8 * j + tq) * AROW + r0];
                afr[mf][1] = As[(8 * j + tq) * AROW + r0 + 8];
                afr[mf][2] = As[(8 * j + tq + 4) * AROW + r0];
                afr[mf][3] = As[(8 * j + tq + 4) * AROW + r0 + 8];
            }
#pragma unroll
            for (int nf = 0; nf < 4; nf++) {
                const int c0 = wn * 32 + nf * 8 + gq;
                bfr[nf][0] = Bsm[(8 * j + tq) * BROW + c0];
                bfr[nf][1] = Bsm[(8 * j + tq + 4) * BROW + c0];
            }
#pragma unroll
            for (int mf = 0; mf < 4; mf++)
#pragma unroll
                for (int nf = 0; nf < 4; nf++)
                    mma16(acc[mf][nf], afr[mf], bfr[nf]);
        }
    }

    const int n0 = bx * 128;
#pragma unroll
    for (int mf = 0; mf < 4; mf++)
#pragma unroll
        for (int nf = 0; nf < 4; nf++) {
            const int row = by * 128 + wm * 64 + mf * 16 + gq;   // = t*B_ + b
            const int col = n0 + wn * 32 + nf * 8 + tq * 2;
            const float b0v = bias[col], b1v = bias[col + 1];
            g_xph[(size_t)row * (G4_ / 2) + (col >> 1)] =
                __floats2half2_rn(acc[mf][nf][0] + b0v, acc[mf][nf][1] + b1v);
            g_xph[(size_t)(row + 8) * (G4_ / 2) + (col >> 1)] =
                __floats2half2_rn(acc[mf][nf][2] + b0v, acc[mf][nf][3] + b1v);
        }
}

// ---------------- stage 2: persistent fp16 recurrent kernel -----------------
// grid (16, 8) = 128 CTAs, 256 thr (8 warps, warp tile 64x32), 1 CTA/SM.
// U resident in smem (swizzled) for all 64 steps; only h streamed per chunk;
// xp (half2) prefetched into smem during first 8 chunks; c in registers.
__global__ void __launch_bounds__(256, 1)
lstm_rec(float* __restrict__ out)
{
    constexpr int AROW = 136;                     // mod 32 == 8
    constexpr int ASTW = 16 * AROW;               // 2176 words per A stage
    constexpr int UOFF = 3 * ASTW;                // 6528 words
    constexpr int XOFF = UOFF + 256 * 128;        // 39296 words
    constexpr int XR2  = 68;                      // xp row stride (half2 words)

    extern __shared__ __align__(16) uint32_t sm[];
    const uint32_t sbase = (uint32_t)__cvta_generic_to_shared(sm);
    const uint32_t* Us = sm + UOFF;
    const uint32_t* xp_sm = sm + XOFF;

    const int tid = threadIdx.x;
    const int bx = blockIdx.x, by = blockIdx.y;

    // ---- load U slice resident (256 k2-rows x 128 cols, rotation swizzle)
    {
#pragma unroll
        for (int i = 0; i < 32; i++) {
            const int q = tid + i * 256;
            const int row = q >> 5, m4 = (q & 31) * 4;
            const int gate = m4 >> 5, hid = m4 & 31;
            const uint32_t dst = (uint32_t)(UOFF + row * 128 + ((m4 + 8 * (row & 3)) & 127));
            cp16(sbase + dst * 4u, g_uh2 + (size_t)row * G4_ + gate * H_ + bx * 32 + hid);
        }
        cpcommit(); cpwait<0>();
        __syncthreads();
    }

    // ---- A (h) loader: 2 cp16/thread per chunk (16 k2 x 128 b = 8KB)
    uint32_t offA[2];
    size_t aoff[2];
#pragma unroll
    for (int c = 0; c < 2; c++) {
        const int q = tid + c * 256;
        const int k2 = q >> 5, m4 = (q & 31) * 4;
        offA[c] = (uint32_t)(k2 * AROW + m4);
        aoff[c] = (size_t)k2 * B_ + by * 128 + m4;
    }

    // ---- xp loader: 1 cp16/thread per chunk for kt<8 (16 rows x 16 chunks)
    const int xrl = tid >> 4;                // 0..15 (row within sub-tile)
    const int xcc = tid & 15;                // 16B chunk in row
    const int xg  = xcc >> 2, xh2 = (xcc & 3) * 4;
    const uint32_t xdst0 = (uint32_t)(XOFF + xrl * XR2 + xg * 16 + xh2);
    const size_t   xsrc0 = ((size_t)(by * 128 + xrl)) * (G4_ / 2) + xg * (H_ / 2) + bx * 16 + xh2;

    const int warp = tid >> 5, lane = tid & 31;
    const int wm = warp >> 2, wn = warp & 3;
    const int gq = lane >> 2, tq = lane & 3;
    const int hidl = wn * 8 + tq * 2;
    const int rotl = (wn * 8 + gq + 8 * tq);  // U swizzle: bank-free B frags

    float cst[4][2][2] = {};                 // cell state, registers only

    for (int t = 0; t < T_; t++) {
        const __half2* hbase = g_h2[t & 1];
        __half2*       hW    = g_h2[(t + 1) & 1];
        const __half2* xpg = g_xph + (size_t)t * B_ * (G4_ / 2);

        float acc[4][4][4] = {};

        auto ISSUE = [&](int kt) {
            const uint32_t sb = sbase + (uint32_t)((kt % 3) * ASTW) * 4u;
#pragma unroll
            for (int c = 0; c < 2; c++)
                cp16(sb + offA[c] * 4u, hbase + aoff[c] + (size_t)kt * 16 * B_);
            if (kt < 8)
                cp16(sbase + (xdst0 + (uint32_t)(16 * kt) * XR2) * 4u,
                     xpg + xsrc0 + (size_t)(16 * kt) * (G4_ / 2));
        };

        ISSUE(0); cpcommit();
        ISSUE(1); cpcommit();

        for (int kt = 0; kt < 16; kt++) {
            cpwait<1>();
            __syncthreads();
            if (kt + 2 < 16) ISSUE(kt + 2);
            cpcommit();

            const uint32_t* As = sm + (kt % 3) * ASTW;
#pragma unroll
            for (int j = 0; j < 2; j++) {
                uint32_t afr[4][4], bfr[4][2];
#pragma unroll
                for (int mf = 0; mf < 4; mf++) {
                    const int r0 = wm * 64 + mf * 16 + gq;
                    afr[mf][0] = As[(8 * j + tq) * AROW + r0];
                    afr[mf][1] = As[(8 * j + tq) * AROW + r0 + 8];
                    afr[mf][2] = As[(8 * j + tq + 4) * AROW + r0];
                    afr[mf][3] = As[(8 * j + tq + 4) * AROW + r0 + 8];
                }
                const int ur0 = (kt * 16 + 8 * j + tq) * 128;
                const int ur1 = ur0 + 4 * 128;
#pragma unroll
                for (int nf = 0; nf < 4; nf++) {
                    const int cc = (nf * 32 + rotl) & 127;
                    bfr[nf][0] = Us[ur0 + cc];
                    bfr[nf][1] = Us[ur1 + cc];
                }
#pragma unroll
                for (int mf = 0; mf < 4; mf++)
#pragma unroll
                    for (int nf = 0; nf < 4; nf++)
                        mma16(acc[mf][nf], afr[mf], bfr[nf]);
            }
        }

        // ---- fused LSTM cell epilogue (xp from smem, c in registers)
#pragma unroll
        for (int mf = 0; mf < 4; mf++) {
#pragma unroll
            for (int rh = 0; rh < 2; rh++) {
                const int rl = wm * 64 + mf * 16 + rh * 8 + gq;   // local batch row
                float z[4][2];
#pragma unroll
                for (int g = 0; g < 4; g++) {
                    const float2 xv = __half22float2(
                        ((const __half2*)xp_sm)[rl * XR2 + g * 16 + (hidl >> 1)]);
                    z[g][0] = acc[mf][g][rh * 2 + 0] + xv.x;
                    z[g][1] = acc[mf][g][rh * 2 + 1] + xv.y;
                }
                float2 hh;
                {
                    const float ii = sigm(z[0][0]), ff = sigm(z[1][0]);
                    const float gg = tanh_(z[2][0]), oo = sigm(z[3][0]);
                    cst[mf][rh][0] = ff * cst[mf][rh][0] + ii * gg;
                    hh.x = oo * tanh_(cst[mf][rh][0]);
                }
                {
                    const float ii = sigm(z[0][1]), ff = sigm(z[1][1]);
                    const float gg = tanh_(z[2][1]), oo = sigm(z[3][1]);
                    cst[mf][rh][1] = ff * cst[mf][rh][1] + ii * gg;
                    hh.y = oo * tanh_(cst[mf][rh][1]);
                }
                const int r = by * 128 + rl;
                *(float2*)&out[((size_t)r * T_ + t) * H_ + bx * 32 + hidl] = hh;
                hW[(size_t)(bx * 16 + (hidl >> 1)) * B_ + r] = __floats2half2_rn(hh.x, hh.y);
            }
        }

        // ---- per-by-group step barrier (16 CTAs)
        __syncthreads();
        if (tid == 0) {
            __threadfence();
            atomicAdd(&g_bar[by], 1u);
            const unsigned tgt = 16u * (unsigned)(t + 1);
            unsigned v;
            do {
                asm volatile("ld.acquire.gpu.u32 %0, [%1];"
                             : "=r"(v) : "l"(&g_bar[by]) : "memory");
                if (v < tgt) __nanosleep(20);
            } while (v < tgt);
        }
        __syncthreads();
    }
}

// ---------------- launch -----------------------------------------------------
extern "C" void kernel_launch(void* const* d_in, const int* in_sizes, int n_in,
                              void* d_out, int out_size)
{
    const float* X    = (const float*)d_in[0];   // [B, T, D]
    const float* W    = (const float*)d_in[1];   // [D, 4H]
    const float* U    = (const float*)d_in[2];   // [H, 4H]
    const float* bias = (const float*)d_in[3];   // [4H]
    float* out = (float*)d_out;                  // [B, T, H]

    constexpr int SM0 = 3 * (16 * 136 + 16 * 136) * 4;              // 52224 B
    constexpr int SM1 = (3 * 16 * 136 + 256 * 128 + 128 * 68) * 4;  // 192000 B
    cudaFuncSetAttribute(gemm_x,   cudaFuncAttributeMaxDynamicSharedMemorySize, SM0);
    cudaFuncSetAttribute(lstm_rec, cudaFuncAttributeMaxDynamicSharedMemorySize, SM1);

    conv_wu<<<((D_ / 2) * G4_) / 256, 256>>>(W, U);
    prep_xh<<<dim3(D_ / 32, B_ / 32, T_), dim3(32, 8)>>>(X);
    zero_state<<<((H_ / 2) * B_) / 256, 256>>>();

    // Stage 1: input projection (128x128 tiles, fp16 operands, half2 output)
    gemm_x<<<dim3(G4_ / 128, (T_ * B_) / 128), 256, SM0>>>(bias);

    // Stage 2: single persistent kernel, 128 CTAs (1/SM), all 64 steps
    lstm_rec<<<dim3(16, 8), 256, SM1>>>(out);
}